// round 12
// baseline (speedup 1.0000x reference)
#include <cuda_runtime.h>
#include <cuda_fp16.h>
#include <cstdint>

// ---------------------------------------------------------------------------
// CrossAttention, fp16 dataflow, cp.async + ldmatrix(+trans) mma.sync GEMMs.
// Softmax denominators applied as half2 fragment scaling inside out_k
// (no separate B-rescale pass).
// ---------------------------------------------------------------------------

namespace {
constexpr int NB = 8, NLA = 2048, NLB = 2048, ND = 512, NH = 512;
constexpr float SCALE = 0.04419417382415922f;   // 1/sqrt(512)
constexpr float EXPM  = 1e-6f;                   // masked-entry E value

constexpr int BM = 128, BN = 128, BK = 32;       // chunk = 2 k16 steps
constexpr int ROWB = 80;                          // operand row pitch (bytes)
constexpr int OPB_STD = BM * ROWB;                // 10240
constexpr int APITCH_T = 272;                     // trans-A pitch (32 rows x 256B)
constexpr int STG_B = 2 * OPB_STD;                // 20480 per stage
constexpr int SMEM4 = 4 * STG_B;                  // 81920  (proj, scores)
constexpr int SMEM5 = 5 * STG_B;                  // 102400 (out)
}

// ---- scratch ----------------------------------------------------------------
__device__ __half g_wat[512 * 512];
__device__ __half g_wbt[512 * 512];
__device__ __half g_iha[NB * 2048 * 512];
__device__ __half g_ihb[NB * 2048 * 512];
__device__ __half g_iat[NB * 512 * 2048];         // input_a^T
__device__ __half g_ibt[NB * 512 * 2048];         // input_b^T
__device__ __half g_ma[NB * NLA * NH];
__device__ __half g_mb[NB * NLB * NH];
__device__ __half g_s [(size_t)NB * NLA * NLB];   // E[i][j]
__device__ float g_rsum[NB * NLA];
__device__ float g_csum[NB * NLB];
__device__ __half g_rinvh[NB * NLA];              // half(1/rsum)
__device__ __half g_cinvh[NB * NLB];              // half(1/csum)

// ---- helpers ------------------------------------------------------------------
__device__ __forceinline__ uint32_t smem_u32(const void* p) {
    uint32_t a;
    asm("{ .reg .u64 t; cvta.to.shared.u64 t, %1; cvt.u32.u64 %0, t; }"
        : "=r"(a) : "l"(p));
    return a;
}
__device__ __forceinline__ void cpa16(uint32_t s, const void* g) {
    asm volatile("cp.async.cg.shared.global [%0], [%1], 16;" :: "r"(s), "l"(g));
}
__device__ __forceinline__ void cpa_commit() {
    asm volatile("cp.async.commit_group;" ::: "memory");
}
__device__ __forceinline__ void cpa_wait2() {
    asm volatile("cp.async.wait_group 2;" ::: "memory");
}
__device__ __forceinline__ void cpa_wait3() {
    asm volatile("cp.async.wait_group 3;" ::: "memory");
}
__device__ __forceinline__ void ldm4(uint32_t (&r)[4], uint32_t a) {
    asm volatile("ldmatrix.sync.aligned.m8n8.x4.shared.b16 {%0,%1,%2,%3}, [%4];"
                 : "=r"(r[0]), "=r"(r[1]), "=r"(r[2]), "=r"(r[3]) : "r"(a));
}
__device__ __forceinline__ void ldm4t(uint32_t (&r)[4], uint32_t a) {
    asm volatile("ldmatrix.sync.aligned.m8n8.x4.trans.shared.b16 {%0,%1,%2,%3}, [%4];"
                 : "=r"(r[0]), "=r"(r[1]), "=r"(r[2]), "=r"(r[3]) : "r"(a));
}
__device__ __forceinline__ void mma_f16(float (&d)[4],
                                        uint32_t a0, uint32_t a1, uint32_t a2, uint32_t a3,
                                        uint32_t b0, uint32_t b1) {
    asm volatile(
        "mma.sync.aligned.m16n8k16.row.col.f32.f16.f16.f32 "
        "{%0,%1,%2,%3}, {%4,%5,%6,%7}, {%8,%9}, {%0,%1,%2,%3};"
        : "+f"(d[0]), "+f"(d[1]), "+f"(d[2]), "+f"(d[3])
        : "r"(a0), "r"(a1), "r"(a2), "r"(a3), "r"(b0), "r"(b1));
}
__device__ __forceinline__ uint32_t hmul2u(uint32_t a, __half2 s) {
    __half2 v = __hmul2(*reinterpret_cast<__half2*>(&a), s);
    return *reinterpret_cast<uint32_t*>(&v);
}

// MMA burst over one fragment buffer (4x8 tiles of 16x8)
#define MMA_BURST(AF, BQ, ACC)                                                  \
    _Pragma("unroll")                                                           \
    for (int mt = 0; mt < 4; ++mt)                                              \
        _Pragma("unroll")                                                       \
        for (int nt = 0; nt < 8; ++nt)                                          \
            mma_f16(ACC[mt][nt], AF[mt][0], AF[mt][1], AF[mt][2], AF[mt][3],    \
                    BQ[nt >> 1][(nt & 1) * 2], BQ[nt >> 1][(nt & 1) * 2 + 1]);

// ---------------------------------------------------------------------------
// proj (merged a/b): C = input @ W^T + bias -> fp16 mapped. z selects set.
// ---------------------------------------------------------------------------
__global__ void __launch_bounds__(128, 2)
proj_k(const float* __restrict__ ba, const float* __restrict__ bb)
{
    constexpr int NC = 512 / BK;
    extern __shared__ __align__(16) char smem_raw[];
    const uint32_t smb = smem_u32(smem_raw);

    const int tid = threadIdx.x;
    const int sel = blockIdx.z;
    const int m0  = blockIdx.y * BM;
    const int n0  = blockIdx.x * BN;

    const __half* Ah = sel ? g_ihb : g_iha;
    const __half* Bh = sel ? g_wbt : g_wat;
    __half*       Ch = sel ? g_mb  : g_ma;
    const float* aux = sel ? bb : ba;

    const int r4 = tid >> 2;
    const int q4 = tid & 3;
    const uint32_t soff = (uint32_t)(r4 * ROWB + q4 * 16);
    const __half* gA = Ah + (size_t)(m0 + r4) * 512 + q4 * 8;
    const __half* gB = Bh + (size_t)(n0 + r4) * 512 + q4 * 8;

    auto issueChunk = [&](int c, int st) {
        const uint32_t sbase = smb + st * STG_B;
        #pragma unroll
        for (int p = 0; p < 4; ++p) {
            cpa16(sbase + soff + p * (32 * ROWB), gA + c * BK + (size_t)p * (32 * 512));
            cpa16(sbase + OPB_STD + soff + p * (32 * ROWB),
                  gB + c * BK + (size_t)p * (32 * 512));
        }
    };

    const int warp = tid >> 5, lane = tid & 31;
    const int wm = warp >> 1, wn = warp & 1;
    const int m_base = wm * 64, n_base = wn * 64;
    const int g = lane >> 2, tg = lane & 3;

    const uint32_t a_row = (uint32_t)(m_base + (lane & 15)) * ROWB + (lane >> 4) * 16;
    const uint32_t b_row = (uint32_t)(n_base + ((lane >> 4) << 3) + (lane & 7)) * ROWB
                         + ((lane >> 3) & 1) * 16;

    float acc[4][8][4] = {};

    #pragma unroll
    for (int c = 0; c < 3; ++c) { issueChunk(c, c); cpa_commit(); }

    for (int c = 0; c < NC; ++c) {
        cpa_wait2();
        __syncthreads();
        const uint32_t ab = smb + (c & 3) * STG_B;
        const uint32_t bb2 = ab + OPB_STD;
        #pragma unroll
        for (int s = 0; s < 2; ++s) {
            uint32_t af[4][4], bq[4][4];
            #pragma unroll
            for (int mt = 0; mt < 4; ++mt)
                ldm4(af[mt], ab + a_row + mt * (16 * ROWB) + s * 32);
            #pragma unroll
            for (int np = 0; np < 4; ++np)
                ldm4(bq[np], bb2 + b_row + np * (16 * ROWB) + s * 32);
            MMA_BURST(af, bq, acc);
        }
        if (c + 3 < NC) issueChunk(c + 3, (c + 3) & 3);
        cpa_commit();
    }

    #pragma unroll
    for (int mt = 0; mt < 4; ++mt) {
        const int row0 = m0 + m_base + 16 * mt + g;
        #pragma unroll
        for (int nt = 0; nt < 8; ++nt) {
            const int col0 = n0 + n_base + 8 * nt + 2 * tg;
            const float2 bv = *(const float2*)(aux + col0);
            *(__half2*)(Ch + (size_t)row0 * 512 + col0) =
                __floats2half2_rn(acc[mt][nt][0] + bv.x, acc[mt][nt][1] + bv.y);
            *(__half2*)(Ch + (size_t)(row0 + 8) * 512 + col0) =
                __floats2half2_rn(acc[mt][nt][2] + bv.x, acc[mt][nt][3] + bv.y);
        }
    }
}

// ---------------------------------------------------------------------------
// scores: E = exp(scale * ma.mb^T), masked -> EXPM; writes g_s + fused sums.
// ---------------------------------------------------------------------------
__global__ void __launch_bounds__(128, 2)
scores_k(const int* __restrict__ MR, const int* __restrict__ MCm)
{
    constexpr int NC = 512 / BK;
    extern __shared__ __align__(16) char smem_raw[];
    const uint32_t smb = smem_u32(smem_raw);

    const int tid = threadIdx.x;
    const int z   = blockIdx.z;
    const int m0  = blockIdx.y * BM;
    const int n0  = blockIdx.x * BN;

    const __half* Ah = g_ma + (size_t)z * 2048 * 512;
    const __half* Bh = g_mb + (size_t)z * 2048 * 512;
    __half*       Ch = g_s  + (size_t)z * NLA * NLB;

    const int r4 = tid >> 2;
    const int q4 = tid & 3;
    const uint32_t soff = (uint32_t)(r4 * ROWB + q4 * 16);
    const __half* gA = Ah + (size_t)(m0 + r4) * 512 + q4 * 8;
    const __half* gB = Bh + (size_t)(n0 + r4) * 512 + q4 * 8;

    auto issueChunk = [&](int c, int st) {
        const uint32_t sbase = smb + st * STG_B;
        #pragma unroll
        for (int p = 0; p < 4; ++p) {
            cpa16(sbase + soff + p * (32 * ROWB), gA + c * BK + (size_t)p * (32 * 512));
            cpa16(sbase + OPB_STD + soff + p * (32 * ROWB),
                  gB + c * BK + (size_t)p * (32 * 512));
        }
    };

    const int warp = tid >> 5, lane = tid & 31;
    const int wm = warp >> 1, wn = warp & 1;
    const int m_base = wm * 64, n_base = wn * 64;
    const int g = lane >> 2, tg = lane & 3;

    const uint32_t a_row = (uint32_t)(m_base + (lane & 15)) * ROWB + (lane >> 4) * 16;
    const uint32_t b_row = (uint32_t)(n_base + ((lane >> 4) << 3) + (lane & 7)) * ROWB
                         + ((lane >> 3) & 1) * 16;

    float acc[4][8][4] = {};
    uint32_t af[2][4][4], bq[2][4][4];

    #pragma unroll
    for (int c = 0; c < 3; ++c) { issueChunk(c, c); cpa_commit(); }

    for (int c = 0; c < NC; ++c) {
        cpa_wait2();
        __syncthreads();
        const uint32_t ab = smb + (c & 3) * STG_B;
        const uint32_t bb2 = ab + OPB_STD;
        #pragma unroll
        for (int s = 0; s < 2; ++s) {
            #pragma unroll
            for (int mt = 0; mt < 4; ++mt)
                ldm4(af[s][mt], ab + a_row + mt * (16 * ROWB) + s * 32);
            #pragma unroll
            for (int np = 0; np < 4; ++np)
                ldm4(bq[s][np], bb2 + b_row + np * (16 * ROWB) + s * 32);
        }
        MMA_BURST(af[0], bq[0], acc);
        if (c + 3 < NC) issueChunk(c + 3, (c + 3) & 3);
        cpa_commit();
        MMA_BURST(af[1], bq[1], acc);
    }

    float csum0[8], csum1[8];
    #pragma unroll
    for (int nt = 0; nt < 8; ++nt) { csum0[nt] = 0.f; csum1[nt] = 0.f; }
    #pragma unroll
    for (int mt = 0; mt < 4; ++mt) {
        const int row0 = m0 + m_base + 16 * mt + g;
        const int rm0 = MR[z * 2048 + row0];
        const int rm1 = MR[z * 2048 + row0 + 8];
        float rsum0 = 0.f, rsum1 = 0.f;
        #pragma unroll
        for (int nt = 0; nt < 8; ++nt) {
            const int col0 = n0 + n_base + 8 * nt + 2 * tg;
            const int2 cm = *(const int2*)&MCm[z * 2048 + col0];
            float e00 = (rm0 * cm.x == 0) ? EXPM : __expf(acc[mt][nt][0] * SCALE);
            float e01 = (rm0 * cm.y == 0) ? EXPM : __expf(acc[mt][nt][1] * SCALE);
            float e10 = (rm1 * cm.x == 0) ? EXPM : __expf(acc[mt][nt][2] * SCALE);
            float e11 = (rm1 * cm.y == 0) ? EXPM : __expf(acc[mt][nt][3] * SCALE);
            __half2 p0 = __floats2half2_rn(e00, e01);
            __half2 p1 = __floats2half2_rn(e10, e11);
            *(__half2*)(Ch + (size_t)row0 * 2048 + col0)       = p0;
            *(__half2*)(Ch + (size_t)(row0 + 8) * 2048 + col0) = p1;
            float2 r0 = __half22float2(p0);
            float2 r1 = __half22float2(p1);
            rsum0 += r0.x + r0.y;
            rsum1 += r1.x + r1.y;
            csum0[nt] += r0.x + r1.x;
            csum1[nt] += r0.y + r1.y;
        }
        rsum0 += __shfl_xor_sync(0xffffffffu, rsum0, 1);
        rsum0 += __shfl_xor_sync(0xffffffffu, rsum0, 2);
        rsum1 += __shfl_xor_sync(0xffffffffu, rsum1, 1);
        rsum1 += __shfl_xor_sync(0xffffffffu, rsum1, 2);
        if (tg == 0) {
            atomicAdd(&g_rsum[z * 2048 + row0],     rsum0);
            atomicAdd(&g_rsum[z * 2048 + row0 + 8], rsum1);
        }
    }
    #pragma unroll
    for (int nt = 0; nt < 8; ++nt) {
        float c0 = csum0[nt], c1 = csum1[nt];
        #pragma unroll
        for (int o = 4; o <= 16; o <<= 1) {
            c0 += __shfl_xor_sync(0xffffffffu, c0, o);
            c1 += __shfl_xor_sync(0xffffffffu, c1, o);
        }
        if (g == 0) {
            const int col0 = n0 + n_base + 8 * nt + 2 * tg;
            atomicAdd(&g_csum[z * 2048 + col0],     c0);
            atomicAdd(&g_csum[z * 2048 + col0 + 1], c1);
        }
    }
}

// ---------------------------------------------------------------------------
// out (merged): z<8 -> out_a = E @ (ibt * cinv) + resid_a ;
//               z>=8 -> out_b = E^T @ (iat * rinv) + resid_b.
// inv applied as half2 scaling on B fragments (k = contraction index).
// 5-stage pipeline (prefetch 4, wait_group 3).
// ---------------------------------------------------------------------------
__global__ void __launch_bounds__(128, 2)
out_k(const float* __restrict__ ia, const float* __restrict__ ib,
      float* __restrict__ OUT)
{
    constexpr int NC = 2048 / BK;
    constexpr int NS = 5;
    extern __shared__ __align__(16) char smem_raw[];
    const uint32_t smb = smem_u32(smem_raw);

    const int tid = threadIdx.x;
    const bool tra = blockIdx.z >= 8;
    const int z   = blockIdx.z & 7;
    const int m0  = blockIdx.y * BM;
    const int n0  = blockIdx.x * BN;

    const __half* Ah = g_s + (size_t)z * NLA * NLB;
    const __half* Bh = (tra ? g_iat : g_ibt) + (size_t)z * ND * 2048;
    const float* aux = (tra ? ib : ia) + (size_t)z * 2048 * ND;
    const __half2* invh = (const __half2*)((tra ? g_rinvh : g_cinvh) + z * 2048);
    float* Cf = OUT + (tra ? (size_t)NB * NLA * ND : 0) + (size_t)z * 2048 * ND;

    // producer geometry
    const int r4 = tid >> 2;
    const int q4 = tid & 3;
    const uint32_t soff = (uint32_t)(r4 * ROWB + q4 * 16);
    const __half* gB = Bh + (size_t)(n0 + r4) * 2048 + q4 * 8;
    const uint32_t soffAT = (uint32_t)(r4 * APITCH_T + q4 * 64);
    const __half* gA_std = Ah + (size_t)(m0 + r4) * 2048 + q4 * 8;
    const __half* gA_tra = Ah + m0 + q4 * 32;

    auto issueChunk = [&](int c, int st) {
        const uint32_t sbase = smb + st * STG_B;
        if (tra) {
            const __half* ga = gA_tra + (size_t)(c * BK + r4) * 2048;
            #pragma unroll
            for (int q = 0; q < 4; ++q)
                cpa16(sbase + soffAT + q * 16, ga + q * 8);
        } else {
            #pragma unroll
            for (int p = 0; p < 4; ++p)
                cpa16(sbase + soff + p * (32 * ROWB),
                      gA_std + c * BK + (size_t)p * (32 * 2048));
        }
        #pragma unroll
        for (int p = 0; p < 4; ++p)
            cpa16(sbase + OPB_STD + soff + p * (32 * ROWB),
                  gB + c * BK + (size_t)p * (32 * 2048));
    };

    const int warp = tid >> 5, lane = tid & 31;
    const int wm = warp >> 1, wn = warp & 1;
    const int m_base = wm * 64, n_base = wn * 64;
    const int g = lane >> 2, tg = lane & 3;

    const uint32_t a_row = (uint32_t)(m_base + (lane & 15)) * ROWB + (lane >> 4) * 16;
    const uint32_t a_row_t = (uint32_t)((lane >> 4) * 8 + (lane & 7)) * APITCH_T
                           + ((lane >> 3) & 1) * 16 + (uint32_t)m_base * 2;
    const uint32_t b_row = (uint32_t)(n_base + ((lane >> 4) << 3) + (lane & 7)) * ROWB
                         + ((lane >> 3) & 1) * 16;

    float acc[4][8][4] = {};

    #pragma unroll
    for (int c = 0; c < 4; ++c) { issueChunk(c, c); cpa_commit(); }

    int cur = 0, nxt = 4;
    for (int c = 0; c < NC; ++c) {
        cpa_wait3();
        __syncthreads();
        const uint32_t ab = smb + cur * STG_B;
        const uint32_t bb2 = ab + OPB_STD;
        #pragma unroll
        for (int s = 0; s < 2; ++s) {
            uint32_t af[4][4], bq[4][4];
            if (tra) {
                #pragma unroll
                for (int mt = 0; mt < 4; ++mt)
                    ldm4t(af[mt], ab + a_row_t + 32 * mt + s * (16 * APITCH_T));
            } else {
                #pragma unroll
                for (int mt = 0; mt < 4; ++mt)
                    ldm4(af[mt], ab + a_row + mt * (16 * ROWB) + s * 32);
            }
            #pragma unroll
            for (int np = 0; np < 4; ++np)
                ldm4(bq[np], bb2 + b_row + np * (16 * ROWB) + s * 32);
            // B fragment scaling by 1/softmax-denominator of the contraction k:
            // regs 0,2 cover k-group 0 (k = 2tg,2tg+1), regs 1,3 cover k+8.
            {
                const __half2 vlo = invh[c * 16 + s * 8 + tg];
                const __half2 vhi = invh[c * 16 + s * 8 + 4 + tg];
                #pragma unroll
                for (int np = 0; np < 4; ++np) {
                    bq[np][0] = hmul2u(bq[np][0], vlo);
                    bq[np][1] = hmul2u(bq[np][1], vhi);
                    bq[np][2] = hmul2u(bq[np][2], vlo);
                    bq[np][3] = hmul2u(bq[np][3], vhi);
                }
            }
            MMA_BURST(af, bq, acc);
        }
        if (c + 4 < NC) issueChunk(c + 4, nxt);
        cpa_commit();
        cur = (cur + 1 == NS) ? 0 : cur + 1;
        nxt = (nxt + 1 == NS) ? 0 : nxt + 1;
    }

    #pragma unroll
    for (int mt = 0; mt < 4; ++mt) {
        const int row0 = m0 + m_base + 16 * mt + g;
        #pragma unroll
        for (int nt = 0; nt < 8; ++nt) {
            const int col0 = n0 + n_base + 8 * nt + 2 * tg;
            const float2 e0 = *(const float2*)(aux + (size_t)row0 * 512 + col0);
            const float2 e1 = *(const float2*)(aux + (size_t)(row0 + 8) * 512 + col0);
            *(float2*)(Cf + (size_t)row0 * 512 + col0) =
                make_float2(acc[mt][nt][0] + e0.x, acc[mt][nt][1] + e0.y);
            *(float2*)(Cf + (size_t)(row0 + 8) * 512 + col0) =
                make_float2(acc[mt][nt][2] + e1.x, acc[mt][nt][3] + e1.y);
        }
    }
}

// ---------------------------------------------------------------------------
// prep (merged): z<16 -> input copy+transpose (z>=8 -> b);
// z==16 -> weight transposes (by<16: Wa, by in [16,32): Wb) + sum zeroing.
// ---------------------------------------------------------------------------
__global__ void __launch_bounds__(256)
prep_k(const float* __restrict__ ia, const float* __restrict__ ib,
       const float* __restrict__ Wa, const float* __restrict__ Wb)
{
    __shared__ float tile[32][33];
    const int zz = blockIdx.z;

    if (zz == 16) {
        const int by = blockIdx.y;
        if (by >= 32) {
            const int lin = ((by - 32) * 16 + blockIdx.x) * 256
                          + threadIdx.y * 32 + threadIdx.x;
            if (lin < NB * 2048) { g_rsum[lin] = 0.f; g_csum[lin] = 0.f; }
            return;
        }
        const float* s = (by < 16) ? Wa : Wb;
        __half* d = (by < 16) ? g_wat : g_wbt;
        const int byy = by & 15;
        int x = blockIdx.x * 32 + threadIdx.x;
        int y = byy * 32 + threadIdx.y;
        #pragma unroll
        for (int j = 0; j < 32; j += 8)
            tile[threadIdx.y + j][threadIdx.x] = s[(size_t)(y + j) * 512 + x];
        __syncthreads();
        x = byy * 32 + threadIdx.x;
        y = blockIdx.x * 32 + threadIdx.y;
        #pragma unroll
        for (int j = 0; j < 32; j += 8)
            d[(size_t)(y + j) * 512 + x] =
                __float2half(tile[threadIdx.x][threadIdx.y + j]);
        return;
    }

    const bool sel = zz >= 8;
    const int z = zz & 7;
    const float* s = (sel ? ib : ia) + (size_t)z * 2048 * 512;
    __half* d = (sel ? g_ibt : g_iat) + (size_t)z * 2048 * 512;
    __half* c = (sel ? g_ihb : g_iha) + (size_t)z * 2048 * 512;

    int x = blockIdx.x * 32 + threadIdx.x;
    int y = blockIdx.y * 32 + threadIdx.y;
    #pragma unroll
    for (int j = 0; j < 32; j += 8) {
        float v = s[(size_t)(y + j) * 512 + x];
        tile[threadIdx.y + j][threadIdx.x] = v;
        c[(size_t)(y + j) * 512 + x] = __float2half(v);
    }
    __syncthreads();
    x = blockIdx.y * 32 + threadIdx.x;
    y = blockIdx.x * 32 + threadIdx.y;
    #pragma unroll
    for (int j = 0; j < 32; j += 8)
        d[(size_t)(y + j) * 2048 + x] = __float2half(tile[threadIdx.x][threadIdx.y + j]);
}

// ---------------------------------------------------------------------------
// recip: half(1/sum) for both softmax denominators (tiny).
// ---------------------------------------------------------------------------
__global__ void __launch_bounds__(256)
recip_k()
{
    const int i = blockIdx.x * 256 + threadIdx.x;
    g_rinvh[i] = __float2half(__frcp_rn(g_rsum[i]));
    g_cinvh[i] = __float2half(__frcp_rn(g_csum[i]));
}

// ---------------------------------------------------------------------------
extern "C" void kernel_launch(void* const* d_in, const int* in_sizes, int n_in,
                              void* d_out, int out_size)
{
    (void)in_sizes; (void)n_in; (void)out_size;
    const float* input_a = (const float*)d_in[0];
    const float* input_b = (const float*)d_in[1];
    const int*   mask_a  = (const int*)d_in[2];
    const int*   mask_b  = (const int*)d_in[3];
    const float* Wa      = (const float*)d_in[4];
    const float* ba      = (const float*)d_in[5];
    const float* Wb      = (const float*)d_in[6];
    const float* bb      = (const float*)d_in[7];
    float* out = (float*)d_out;

    static bool attr_done = false;
    if (!attr_done) {
        cudaFuncSetAttribute(proj_k,   cudaFuncAttributeMaxDynamicSharedMemorySize, SMEM4);
        cudaFuncSetAttribute(scores_k, cudaFuncAttributeMaxDynamicSharedMemorySize, SMEM4);
        cudaFuncSetAttribute(out_k,    cudaFuncAttributeMaxDynamicSharedMemorySize, SMEM5);
        attr_done = true;
    }

    // prep: weight + input transposes, fp16 copies, sum zeroing (one launch)
    prep_k<<<dim3(16, 64, 17), dim3(32, 8)>>>(input_a, input_b, Wa, Wb);

    // projections (a+b merged) -> fp16 mapped
    proj_k<<<dim3(4, 128, 2), 128, SMEM4>>>(ba, bb);

    // masked exp-scores -> g_s (fp16) + fused row/col sums
    scores_k<<<dim3(16, 16, NB), 128, SMEM4>>>(mask_a, mask_b);

    // half reciprocals of the denominators (tiny)
    recip_k<<<NB * 2048 / 256, 256>>>();

    // attention-weighted outputs + residual (a+b merged), inv folded in-register
    out_k<<<dim3(4, 16, 16), 128, SMEM5>>>(input_a, input_b, out);
}

// round 13
// speedup vs baseline: 1.1029x; 1.1029x over previous
#include <cuda_runtime.h>
#include <cuda_fp16.h>
#include <cstdint>

// ---------------------------------------------------------------------------
// CrossAttention, fp16 dataflow, cp.async + ldmatrix(+trans) mma.sync GEMMs.
// proj reads A from transposed inputs via ldmatrix.trans (no fp16 input copy);
// scaleb: register-cached inv, streaming rewrite.
// ---------------------------------------------------------------------------

namespace {
constexpr int NB = 8, NLA = 2048, NLB = 2048, ND = 512, NH = 512;
constexpr float SCALE = 0.04419417382415922f;   // 1/sqrt(512)
constexpr float EXPM  = 1e-6f;                   // masked-entry E value

constexpr int BM = 128, BN = 128, BK = 32;       // chunk = 2 k16 steps
constexpr int ROWB = 80;                          // operand row pitch (bytes)
constexpr int OPB_STD = BM * ROWB;                // 10240
constexpr int APITCH_T = 272;                     // trans-A pitch (32 rows x 256B)
constexpr int STG_B = 2 * OPB_STD;                // 20480 per stage
constexpr int SMEM4 = 4 * STG_B;                  // 81920  (proj, scores)
constexpr int SMEM5 = 5 * STG_B;                  // 102400 (out)
}

// ---- scratch ----------------------------------------------------------------
__device__ __half g_wat[512 * 512];
__device__ __half g_wbt[512 * 512];
__device__ __half g_iat[NB * 512 * 2048];         // input_a^T (later *rinv)
__device__ __half g_ibt[NB * 512 * 2048];         // input_b^T (later *cinv)
__device__ __half g_ma[NB * NLA * NH];
__device__ __half g_mb[NB * NLB * NH];
__device__ __half g_s [(size_t)NB * NLA * NLB];   // E[i][j]
__device__ float g_rsum[NB * NLA];
__device__ float g_csum[NB * NLB];

// ---- helpers ------------------------------------------------------------------
__device__ __forceinline__ uint32_t smem_u32(const void* p) {
    uint32_t a;
    asm("{ .reg .u64 t; cvta.to.shared.u64 t, %1; cvt.u32.u64 %0, t; }"
        : "=r"(a) : "l"(p));
    return a;
}
__device__ __forceinline__ void cpa16(uint32_t s, const void* g) {
    asm volatile("cp.async.cg.shared.global [%0], [%1], 16;" :: "r"(s), "l"(g));
}
__device__ __forceinline__ void cpa_commit() {
    asm volatile("cp.async.commit_group;" ::: "memory");
}
__device__ __forceinline__ void cpa_wait2() {
    asm volatile("cp.async.wait_group 2;" ::: "memory");
}
__device__ __forceinline__ void cpa_wait3() {
    asm volatile("cp.async.wait_group 3;" ::: "memory");
}
__device__ __forceinline__ void ldm4(uint32_t (&r)[4], uint32_t a) {
    asm volatile("ldmatrix.sync.aligned.m8n8.x4.shared.b16 {%0,%1,%2,%3}, [%4];"
                 : "=r"(r[0]), "=r"(r[1]), "=r"(r[2]), "=r"(r[3]) : "r"(a));
}
__device__ __forceinline__ void ldm4t(uint32_t (&r)[4], uint32_t a) {
    asm volatile("ldmatrix.sync.aligned.m8n8.x4.trans.shared.b16 {%0,%1,%2,%3}, [%4];"
                 : "=r"(r[0]), "=r"(r[1]), "=r"(r[2]), "=r"(r[3]) : "r"(a));
}
__device__ __forceinline__ void mma_f16(float (&d)[4],
                                        uint32_t a0, uint32_t a1, uint32_t a2, uint32_t a3,
                                        uint32_t b0, uint32_t b1) {
    asm volatile(
        "mma.sync.aligned.m16n8k16.row.col.f32.f16.f16.f32 "
        "{%0,%1,%2,%3}, {%4,%5,%6,%7}, {%8,%9}, {%0,%1,%2,%3};"
        : "+f"(d[0]), "+f"(d[1]), "+f"(d[2]), "+f"(d[3])
        : "r"(a0), "r"(a1), "r"(a2), "r"(a3), "r"(b0), "r"(b1));
}

// MMA burst over one fragment buffer (4x8 tiles of 16x8)
#define MMA_BURST(AF, BQ, ACC)                                                  \
    _Pragma("unroll")                                                           \
    for (int mt = 0; mt < 4; ++mt)                                              \
        _Pragma("unroll")                                                       \
        for (int nt = 0; nt < 8; ++nt)                                          \
            mma_f16(ACC[mt][nt], AF[mt][0], AF[mt][1], AF[mt][2], AF[mt][3],    \
                    BQ[nt >> 1][(nt & 1) * 2], BQ[nt >> 1][(nt & 1) * 2 + 1]);

// ---------------------------------------------------------------------------
// proj (merged a/b): C = input @ W^T + bias -> fp16 mapped. z selects set.
// A operand read from transposed input (g_iat/g_ibt) via ldmatrix.trans.
// ---------------------------------------------------------------------------
__global__ void __launch_bounds__(128, 2)
proj_k(const float* __restrict__ ba, const float* __restrict__ bb)
{
    constexpr int NC = 512 / BK;
    extern __shared__ __align__(16) char smem_raw[];
    const uint32_t smb = smem_u32(smem_raw);

    const int tid = threadIdx.x;
    const int sel = blockIdx.z;
    const int m0  = blockIdx.y * BM;      // global token index over NB*2048
    const int n0  = blockIdx.x * BN;

    const int zb   = m0 >> 11;            // batch of this m-block
    const int mloc = m0 & 2047;
    const __half* At = (sel ? g_ibt : g_iat) + (size_t)zb * 512 * 2048;
    const __half* Bh = sel ? g_wbt : g_wat;
    __half*       Ch = sel ? g_mb  : g_ma;
    const float* aux = sel ? bb : ba;

    const int r4 = tid >> 2;              // 0..31 (k-row within chunk)
    const int q4 = tid & 3;
    const uint32_t soffAT = (uint32_t)(r4 * APITCH_T + q4 * 64);
    const __half* gA_tra = At + mloc + q4 * 32;
    const uint32_t soffB = (uint32_t)(r4 * 4 * ROWB);  // unused pattern base (B below)
    const int br = tid >> 2;              // 0..31
    const uint32_t soffB2 = (uint32_t)(br * ROWB + q4 * 16);
    const __half* gB = Bh + (size_t)(n0 + br) * 512 + q4 * 8;

    auto issueChunk = [&](int c, int st) {
        const uint32_t sbase = smb + st * STG_B;
        const __half* ga = gA_tra + (size_t)(c * BK + r4) * 2048;
        #pragma unroll
        for (int q = 0; q < 4; ++q)
            cpa16(sbase + soffAT + q * 16, ga + q * 8);
        #pragma unroll
        for (int p = 0; p < 4; ++p)
            cpa16(sbase + OPB_STD + soffB2 + p * (32 * ROWB),
                  gB + c * BK + (size_t)p * (32 * 512));
    };

    const int warp = tid >> 5, lane = tid & 31;
    const int wm = warp >> 1, wn = warp & 1;
    const int m_base = wm * 64, n_base = wn * 64;
    const int g = lane >> 2, tg = lane & 3;

    const uint32_t a_row_t = (uint32_t)((lane >> 4) * 8 + (lane & 7)) * APITCH_T
                           + ((lane >> 3) & 1) * 16 + (uint32_t)m_base * 2;
    const uint32_t b_row = (uint32_t)(n_base + ((lane >> 4) << 3) + (lane & 7)) * ROWB
                         + ((lane >> 3) & 1) * 16;

    float acc[4][8][4] = {};

    #pragma unroll
    for (int c = 0; c < 3; ++c) { issueChunk(c, c); cpa_commit(); }

    for (int c = 0; c < NC; ++c) {
        cpa_wait2();
        __syncthreads();
        const uint32_t ab = smb + (c & 3) * STG_B;
        const uint32_t bb2 = ab + OPB_STD;
        #pragma unroll
        for (int s = 0; s < 2; ++s) {
            uint32_t af[4][4], bq[4][4];
            #pragma unroll
            for (int mt = 0; mt < 4; ++mt)
                ldm4t(af[mt], ab + a_row_t + 32 * mt + s * (16 * APITCH_T));
            #pragma unroll
            for (int np = 0; np < 4; ++np)
                ldm4(bq[np], bb2 + b_row + np * (16 * ROWB) + s * 32);
            MMA_BURST(af, bq, acc);
        }
        if (c + 3 < NC) issueChunk(c + 3, (c + 3) & 3);
        cpa_commit();
    }

    #pragma unroll
    for (int mt = 0; mt < 4; ++mt) {
        const int row0 = m0 + m_base + 16 * mt + g;
        #pragma unroll
        for (int nt = 0; nt < 8; ++nt) {
            const int col0 = n0 + n_base + 8 * nt + 2 * tg;
            const float2 bv = *(const float2*)(aux + col0);
            *(__half2*)(Ch + (size_t)row0 * 512 + col0) =
                __floats2half2_rn(acc[mt][nt][0] + bv.x, acc[mt][nt][1] + bv.y);
            *(__half2*)(Ch + (size_t)(row0 + 8) * 512 + col0) =
                __floats2half2_rn(acc[mt][nt][2] + bv.x, acc[mt][nt][3] + bv.y);
        }
    }
}

// ---------------------------------------------------------------------------
// scores: E = exp(scale * ma.mb^T), masked -> EXPM; writes g_s + fused sums.
// ---------------------------------------------------------------------------
__global__ void __launch_bounds__(128, 2)
scores_k(const int* __restrict__ MR, const int* __restrict__ MCm)
{
    constexpr int NC = 512 / BK;
    extern __shared__ __align__(16) char smem_raw[];
    const uint32_t smb = smem_u32(smem_raw);

    const int tid = threadIdx.x;
    const int z   = blockIdx.z;
    const int m0  = blockIdx.y * BM;
    const int n0  = blockIdx.x * BN;

    const __half* Ah = g_ma + (size_t)z * 2048 * 512;
    const __half* Bh = g_mb + (size_t)z * 2048 * 512;
    __half*       Ch = g_s  + (size_t)z * NLA * NLB;

    const int r4 = tid >> 2;
    const int q4 = tid & 3;
    const uint32_t soff = (uint32_t)(r4 * ROWB + q4 * 16);
    const __half* gA = Ah + (size_t)(m0 + r4) * 512 + q4 * 8;
    const __half* gB = Bh + (size_t)(n0 + r4) * 512 + q4 * 8;

    auto issueChunk = [&](int c, int st) {
        const uint32_t sbase = smb + st * STG_B;
        #pragma unroll
        for (int p = 0; p < 4; ++p) {
            cpa16(sbase + soff + p * (32 * ROWB), gA + c * BK + (size_t)p * (32 * 512));
            cpa16(sbase + OPB_STD + soff + p * (32 * ROWB),
                  gB + c * BK + (size_t)p * (32 * 512));
        }
    };

    const int warp = tid >> 5, lane = tid & 31;
    const int wm = warp >> 1, wn = warp & 1;
    const int m_base = wm * 64, n_base = wn * 64;
    const int g = lane >> 2, tg = lane & 3;

    const uint32_t a_row = (uint32_t)(m_base + (lane & 15)) * ROWB + (lane >> 4) * 16;
    const uint32_t b_row = (uint32_t)(n_base + ((lane >> 4) << 3) + (lane & 7)) * ROWB
                         + ((lane >> 3) & 1) * 16;

    float acc[4][8][4] = {};
    uint32_t af[2][4][4], bq[2][4][4];

    #pragma unroll
    for (int c = 0; c < 3; ++c) { issueChunk(c, c); cpa_commit(); }

    for (int c = 0; c < NC; ++c) {
        cpa_wait2();
        __syncthreads();
        const uint32_t ab = smb + (c & 3) * STG_B;
        const uint32_t bb2 = ab + OPB_STD;
        #pragma unroll
        for (int s = 0; s < 2; ++s) {
            #pragma unroll
            for (int mt = 0; mt < 4; ++mt)
                ldm4(af[s][mt], ab + a_row + mt * (16 * ROWB) + s * 32);
            #pragma unroll
            for (int np = 0; np < 4; ++np)
                ldm4(bq[s][np], bb2 + b_row + np * (16 * ROWB) + s * 32);
        }
        MMA_BURST(af[0], bq[0], acc);
        if (c + 3 < NC) issueChunk(c + 3, (c + 3) & 3);
        cpa_commit();
        MMA_BURST(af[1], bq[1], acc);
    }

    float csum0[8], csum1[8];
    #pragma unroll
    for (int nt = 0; nt < 8; ++nt) { csum0[nt] = 0.f; csum1[nt] = 0.f; }
    #pragma unroll
    for (int mt = 0; mt < 4; ++mt) {
        const int row0 = m0 + m_base + 16 * mt + g;
        const int rm0 = MR[z * 2048 + row0];
        const int rm1 = MR[z * 2048 + row0 + 8];
        float rsum0 = 0.f, rsum1 = 0.f;
        #pragma unroll
        for (int nt = 0; nt < 8; ++nt) {
            const int col0 = n0 + n_base + 8 * nt + 2 * tg;
            const int2 cm = *(const int2*)&MCm[z * 2048 + col0];
            float e00 = (rm0 * cm.x == 0) ? EXPM : __expf(acc[mt][nt][0] * SCALE);
            float e01 = (rm0 * cm.y == 0) ? EXPM : __expf(acc[mt][nt][1] * SCALE);
            float e10 = (rm1 * cm.x == 0) ? EXPM : __expf(acc[mt][nt][2] * SCALE);
            float e11 = (rm1 * cm.y == 0) ? EXPM : __expf(acc[mt][nt][3] * SCALE);
            __half2 p0 = __floats2half2_rn(e00, e01);
            __half2 p1 = __floats2half2_rn(e10, e11);
            *(__half2*)(Ch + (size_t)row0 * 2048 + col0)       = p0;
            *(__half2*)(Ch + (size_t)(row0 + 8) * 2048 + col0) = p1;
            float2 r0 = __half22float2(p0);
            float2 r1 = __half22float2(p1);
            rsum0 += r0.x + r0.y;
            rsum1 += r1.x + r1.y;
            csum0[nt] += r0.x + r1.x;
            csum1[nt] += r0.y + r1.y;
        }
        rsum0 += __shfl_xor_sync(0xffffffffu, rsum0, 1);
        rsum0 += __shfl_xor_sync(0xffffffffu, rsum0, 2);
        rsum1 += __shfl_xor_sync(0xffffffffu, rsum1, 1);
        rsum1 += __shfl_xor_sync(0xffffffffu, rsum1, 2);
        if (tg == 0) {
            atomicAdd(&g_rsum[z * 2048 + row0],     rsum0);
            atomicAdd(&g_rsum[z * 2048 + row0 + 8], rsum1);
        }
    }
    #pragma unroll
    for (int nt = 0; nt < 8; ++nt) {
        float c0 = csum0[nt], c1 = csum1[nt];
        #pragma unroll
        for (int o = 4; o <= 16; o <<= 1) {
            c0 += __shfl_xor_sync(0xffffffffu, c0, o);
            c1 += __shfl_xor_sync(0xffffffffu, c1, o);
        }
        if (g == 0) {
            const int col0 = n0 + n_base + 8 * nt + 2 * tg;
            atomicAdd(&g_csum[z * 2048 + col0],     c0);
            atomicAdd(&g_csum[z * 2048 + col0 + 1], c1);
        }
    }
}

// ---------------------------------------------------------------------------
// out (merged): z<8 -> out_a = E @ ibt + resid_a ; z>=8 -> out_b = E^T @ iat.
// 5-stage pipeline (prefetch 4, wait_group 3), single fragment buffer.
// ---------------------------------------------------------------------------
__global__ void __launch_bounds__(128, 2)
out_k(const float* __restrict__ ia, const float* __restrict__ ib,
      float* __restrict__ OUT)
{
    constexpr int NC = 2048 / BK;
    constexpr int NS = 5;
    extern __shared__ __align__(16) char smem_raw[];
    const uint32_t smb = smem_u32(smem_raw);

    const int tid = threadIdx.x;
    const bool tra = blockIdx.z >= 8;
    const int z   = blockIdx.z & 7;
    const int m0  = blockIdx.y * BM;
    const int n0  = blockIdx.x * BN;

    const __half* Ah = g_s + (size_t)z * NLA * NLB;
    const __half* Bh = (tra ? g_iat : g_ibt) + (size_t)z * ND * 2048;
    const float* aux = (tra ? ib : ia) + (size_t)z * 2048 * ND;
    float* Cf = OUT + (tra ? (size_t)NB * NLA * ND : 0) + (size_t)z * 2048 * ND;

    // producer geometry
    const int r4 = tid >> 2;
    const int q4 = tid & 3;
    const uint32_t soff = (uint32_t)(r4 * ROWB + q4 * 16);
    const __half* gB = Bh + (size_t)(n0 + r4) * 2048 + q4 * 8;
    const uint32_t soffAT = (uint32_t)(r4 * APITCH_T + q4 * 64);
    const __half* gA_std = Ah + (size_t)(m0 + r4) * 2048 + q4 * 8;
    const __half* gA_tra = Ah + m0 + q4 * 32;

    auto issueChunk = [&](int c, int st) {
        const uint32_t sbase = smb + st * STG_B;
        if (tra) {
            const __half* ga = gA_tra + (size_t)(c * BK + r4) * 2048;
            #pragma unroll
            for (int q = 0; q < 4; ++q)
                cpa16(sbase + soffAT + q * 16, ga + q * 8);
        } else {
            #pragma unroll
            for (int p = 0; p < 4; ++p)
                cpa16(sbase + soff + p * (32 * ROWB),
                      gA_std + c * BK + (size_t)p * (32 * 2048));
        }
        #pragma unroll
        for (int p = 0; p < 4; ++p)
            cpa16(sbase + OPB_STD + soff + p * (32 * ROWB),
                  gB + c * BK + (size_t)p * (32 * 2048));
    };

    const int warp = tid >> 5, lane = tid & 31;
    const int wm = warp >> 1, wn = warp & 1;
    const int m_base = wm * 64, n_base = wn * 64;
    const int g = lane >> 2, tg = lane & 3;

    const uint32_t a_row = (uint32_t)(m_base + (lane & 15)) * ROWB + (lane >> 4) * 16;
    const uint32_t a_row_t = (uint32_t)((lane >> 4) * 8 + (lane & 7)) * APITCH_T
                           + ((lane >> 3) & 1) * 16 + (uint32_t)m_base * 2;
    const uint32_t b_row = (uint32_t)(n_base + ((lane >> 4) << 3) + (lane & 7)) * ROWB
                         + ((lane >> 3) & 1) * 16;

    float acc[4][8][4] = {};

    #pragma unroll
    for (int c = 0; c < 4; ++c) { issueChunk(c, c); cpa_commit(); }

    int cur = 0, nxt = 4;
    for (int c = 0; c < NC; ++c) {
        cpa_wait3();
        __syncthreads();
        const uint32_t ab = smb + cur * STG_B;
        const uint32_t bb2 = ab + OPB_STD;
        #pragma unroll
        for (int s = 0; s < 2; ++s) {
            uint32_t af[4][4], bq[4][4];
            if (tra) {
                #pragma unroll
                for (int mt = 0; mt < 4; ++mt)
                    ldm4t(af[mt], ab + a_row_t + 32 * mt + s * (16 * APITCH_T));
            } else {
                #pragma unroll
                for (int mt = 0; mt < 4; ++mt)
                    ldm4(af[mt], ab + a_row + mt * (16 * ROWB) + s * 32);
            }
            #pragma unroll
            for (int np = 0; np < 4; ++np)
                ldm4(bq[np], bb2 + b_row + np * (16 * ROWB) + s * 32);
            MMA_BURST(af, bq, acc);
        }
        if (c + 4 < NC) issueChunk(c + 4, nxt);
        cpa_commit();
        cur = (cur + 1 == NS) ? 0 : cur + 1;
        nxt = (nxt + 1 == NS) ? 0 : nxt + 1;
    }

    #pragma unroll
    for (int mt = 0; mt < 4; ++mt) {
        const int row0 = m0 + m_base + 16 * mt + g;
        #pragma unroll
        for (int nt = 0; nt < 8; ++nt) {
            const int col0 = n0 + n_base + 8 * nt + 2 * tg;
            const float2 e0 = *(const float2*)(aux + (size_t)row0 * 512 + col0);
            const float2 e1 = *(const float2*)(aux + (size_t)(row0 + 8) * 512 + col0);
            *(float2*)(Cf + (size_t)row0 * 512 + col0) =
                make_float2(acc[mt][nt][0] + e0.x, acc[mt][nt][1] + e0.y);
            *(float2*)(Cf + (size_t)(row0 + 8) * 512 + col0) =
                make_float2(acc[mt][nt][2] + e1.x, acc[mt][nt][3] + e1.y);
        }
    }
}

// ---------------------------------------------------------------------------
// prep (merged): z<16 -> input transpose (z>=8 -> b);
// z==16 -> weight transposes (by<16: Wa, by in [16,32): Wb) + sum zeroing.
// ---------------------------------------------------------------------------
__global__ void __launch_bounds__(256)
prep_k(const float* __restrict__ ia, const float* __restrict__ ib,
       const float* __restrict__ Wa, const float* __restrict__ Wb)
{
    __shared__ float tile[32][33];
    const int zz = blockIdx.z;

    if (zz == 16) {
        const int by = blockIdx.y;
        if (by >= 32) {
            const int lin = ((by - 32) * 16 + blockIdx.x) * 256
                          + threadIdx.y * 32 + threadIdx.x;
            if (lin < NB * 2048) { g_rsum[lin] = 0.f; g_csum[lin] = 0.f; }
            return;
        }
        const float* s = (by < 16) ? Wa : Wb;
        __half* d = (by < 16) ? g_wat : g_wbt;
        const int byy = by & 15;
        int x = blockIdx.x * 32 + threadIdx.x;
        int y = byy * 32 + threadIdx.y;
        #pragma unroll
        for (int j = 0; j < 32; j += 8)
            tile[threadIdx.y + j][threadIdx.x] = s[(size_t)(y + j) * 512 + x];
        __syncthreads();
        x = byy * 32 + threadIdx.x;
        y = blockIdx.x * 32 + threadIdx.y;
        #pragma unroll
        for (int j = 0; j < 32; j += 8)
            d[(size_t)(y + j) * 512 + x] =
                __float2half(tile[threadIdx.x][threadIdx.y + j]);
        return;
    }

    const bool sel = zz >= 8;
    const int z = zz & 7;
    const float* s = (sel ? ib : ia) + (size_t)z * 2048 * 512;
    __half* d = (sel ? g_ibt : g_iat) + (size_t)z * 2048 * 512;

    int x = blockIdx.x * 32 + threadIdx.x;
    int y = blockIdx.y * 32 + threadIdx.y;
    #pragma unroll
    for (int j = 0; j < 32; j += 8)
        tile[threadIdx.y + j][threadIdx.x] = s[(size_t)(y + j) * 512 + x];
    __syncthreads();
    x = blockIdx.y * 32 + threadIdx.x;
    y = blockIdx.x * 32 + threadIdx.y;
    #pragma unroll
    for (int j = 0; j < 32; j += 8)
        d[(size_t)(y + j) * 2048 + x] = __float2half(tile[threadIdx.x][threadIdx.y + j]);
}

// ---------------------------------------------------------------------------
// scaleb (+fused recip): g_ibt *= 1/csum (y=0), g_iat *= 1/rsum (y=1).
// Thread owns 8 j-columns (inv in regs), sweeps 32 d-rows of 16B. Coalesced.
// grid (16, 2, NB), block 256.
// ---------------------------------------------------------------------------
__global__ void __launch_bounds__(256)
scaleb_k()
{
    const int z = blockIdx.z;
    const int j8 = threadIdx.x * 8;                  // 256 threads x 8 = 2048 j
    const int d0 = blockIdx.x * 32;                  // 16 blocks x 32 = 512 d
    __half* base = (blockIdx.y ? g_iat : g_ibt)
                 + (size_t)z * 512 * 2048 + (size_t)d0 * 2048 + j8;
    const float* sum = (blockIdx.y ? g_rsum : g_csum) + z * 2048 + j8;

    __half2 invh[4];
    #pragma unroll
    for (int q = 0; q < 4; ++q)
        invh[q] = __floats2half2_rn(__frcp_rn(sum[2 * q]), __frcp_rn(sum[2 * q + 1]));

    #pragma unroll 4
    for (int d = 0; d < 32; ++d) {
        uint4 v = *(uint4*)(base + (size_t)d * 2048);
        __half2* hp = (__half2*)&v;
        #pragma unroll
        for (int q = 0; q < 4; ++q) hp[q] = __hmul2(hp[q], invh[q]);
        *(uint4*)(base + (size_t)d * 2048) = v;
    }
}

// ---------------------------------------------------------------------------
extern "C" void kernel_launch(void* const* d_in, const int* in_sizes, int n_in,
                              void* d_out, int out_size)
{
    (void)in_sizes; (void)n_in; (void)out_size;
    const float* input_a = (const float*)d_in[0];
    const float* input_b = (const float*)d_in[1];
    const int*   mask_a  = (const int*)d_in[2];
    const int*   mask_b  = (const int*)d_in[3];
    const float* Wa      = (const float*)d_in[4];
    const float* ba      = (const float*)d_in[5];
    const float* Wb      = (const float*)d_in[6];
    const float* bb      = (const float*)d_in[7];
    float* out = (float*)d_out;

    static bool attr_done = false;
    if (!attr_done) {
        cudaFuncSetAttribute(proj_k,   cudaFuncAttributeMaxDynamicSharedMemorySize, SMEM4);
        cudaFuncSetAttribute(scores_k, cudaFuncAttributeMaxDynamicSharedMemorySize, SMEM4);
        cudaFuncSetAttribute(out_k,    cudaFuncAttributeMaxDynamicSharedMemorySize, SMEM5);
        attr_done = true;
    }

    // prep: weight + input transposes, sum zeroing (one launch)
    prep_k<<<dim3(16, 64, 17), dim3(32, 8)>>>(input_a, input_b, Wa, Wb);

    // projections (a+b merged) -> fp16 mapped (A via transposed inputs)
    proj_k<<<dim3(4, 128, 2), 128, SMEM4>>>(ba, bb);

    // masked exp-scores -> g_s (fp16) + fused row/col sums
    scores_k<<<dim3(16, 16, NB), 128, SMEM4>>>(mask_a, mask_b);

    // fold 1/sums into B operands (streaming, inv cached in regs)
    scaleb_k<<<dim3(16, 2, NB), 256>>>();

    // attention-weighted outputs + residual (a+b merged)
    out_k<<<dim3(4, 16, 16), 128, SMEM5>>>(input_a, input_b, out);
}